// round 7
// baseline (speedup 1.0000x reference)
#include <cuda_runtime.h>
#include <math.h>

// ---------------------------------------------------------------------------
// CBiAFormerBlock: B=2, DIM=256, H=W=64, HEADS=8, HG=2, GC=128, HC=32,
// STRIDE=2, WS=8, RH=RW=32 (R=1024), WH=WW=8 (NW=64), WT=64, MLP_HID=1024.
//
// Key restructure vs naive: 1x1 k/v convs commute with bilinear sampling
// (both linear). Project xa per offset-group first (K=128 GEMMs), then
// sample the projected maps directly into kk/vv. Kills the two
// 256x65536x256 GEMMs and the 134MB samp buffer.
// ---------------------------------------------------------------------------

// ------------------------- scratch (device globals) ------------------------
__device__ float  g_xa  [2097152];    // LN1(x)          (B,256,64,64)
__device__ float  g_q   [2097152];    // q conv          (B,256,64,64)
__device__ float  g_t1  [524288];     // dw1             (4,128,32,32)
__device__ float  g_t2  [131072];     // dw2             (4,128,16,16)
__device__ float  g_t3  [32768];      // dw3 + bn/gelu   (4,128,8,8)
__device__ float  g_off [524288];     // off4 gemm       (4,2048,64)
__device__ float2 g_pos [262144];     // sample coords   (4,64,1024)
__device__ float  g_kxa [4194304];    // k_w@xa per grp  (B,2,256,64,64)
__device__ float  g_vxa [4194304];    // v_w@xa per grp  (B,2,256,64,64)
__device__ float  g_kk  [33554432];   // sampled k       (B,256,64,1024)
__device__ float  g_vv  [33554432];   // sampled v       (B,256,64,1024)
__device__ float  g_ao  [2097152];    // attn out        (B,256,64,64)
__device__ float  g_x1  [2097152];    // x + proj
__device__ float  g_xm  [2097152];    // LN2(x1)
__device__ float  g_hdn [8388608];    // mlp hidden      (B,1024,64,64)

__device__ __forceinline__ float gelu_f(float v) {
    return 0.5f * v * (1.0f + erff(v * 0.7071067811865476f));
}

// ---------------------------------------------------------------------------
// LayerNorm over channel dim (256) per pixel. grid(64, B), block 64 (x-pixel)
// ---------------------------------------------------------------------------
__global__ void ln_kernel(const float* __restrict__ x, const float* __restrict__ g,
                          const float* __restrict__ bb, float* __restrict__ out)
{
    int px = threadIdx.x;             // 0..63 (x)
    int y  = blockIdx.x;
    int b  = blockIdx.y;
    const float* base = x + (size_t)b * 1048576 + y * 64 + px;
    float s = 0.f, s2 = 0.f;
    #pragma unroll 4
    for (int c = 0; c < 256; c++) {
        float v = base[(size_t)c * 4096];
        s += v; s2 += v * v;
    }
    float mu   = s * (1.0f / 256.0f);
    float var  = s2 * (1.0f / 256.0f) - mu * mu;
    float rstd = rsqrtf(var + 1e-5f);
    float* ob = out + (size_t)b * 1048576 + y * 64 + px;
    #pragma unroll 4
    for (int c = 0; c < 256; c++) {
        float v = base[(size_t)c * 4096];
        ob[(size_t)c * 4096] = (v - mu) * rstd * g[c] + bb[c];
    }
}

// ---------------------------------------------------------------------------
// Generic SGEMM: C[M,N] = act(A[M,K] @ B[K,N] + bias[M]) (+res)
// ACT: 0=none, 1=gelu, 2=residual add. K % 16 == 0 (always here).
// A row stride lda, B row stride ldb, C row stride N.
// 128x128 tile, BK=16, 256 threads, 8x8 register tile (4+4 split addressing).
// grid: (ceil(N/128), ceil(M/128), batch)
// ---------------------------------------------------------------------------
template<int ACT>
__global__ __launch_bounds__(256, 2)
void sgemm_kernel(const float* __restrict__ A, const float* __restrict__ B,
                  float* __restrict__ C, const float* __restrict__ bias,
                  const float* __restrict__ res,
                  int M, int N, int K, int lda, int ldb,
                  long long sA, long long sB, long long sC, long long sR)
{
    __shared__ float As[16][132];
    __shared__ float Bs[16][128];

    int bz = blockIdx.z;
    A += bz * sA; B += bz * sB; C += bz * sC;
    if (ACT == 2) res += bz * sR;

    int n0 = blockIdx.x * 128, m0 = blockIdx.y * 128;
    int t  = threadIdx.x;
    int tx = t & 15, ty = t >> 4;

    float acc[8][8];
    #pragma unroll
    for (int i = 0; i < 8; i++)
        #pragma unroll
        for (int j = 0; j < 8; j++) acc[i][j] = 0.f;

    int ar = t >> 1, ks = (t & 1) * 8;     // A loader: row ar, 8 consecutive k
    int br = t >> 4, bc = (t & 15) * 8;    // B loader: k-row br, 8 cols

    for (int k0 = 0; k0 < K; k0 += 16) {
        int arow = m0 + ar;
        const float* ap = A + (size_t)arow * lda + k0 + ks;
        #pragma unroll
        for (int i = 0; i < 8; i++)
            As[ks + i][ar] = (arow < M) ? ap[i] : 0.f;

        const float* bp = B + (size_t)(k0 + br) * ldb + n0 + bc;
        #pragma unroll
        for (int i = 0; i < 8; i++)
            Bs[br][bc + i] = (n0 + bc + i < N) ? bp[i] : 0.f;

        __syncthreads();
        #pragma unroll
        for (int k = 0; k < 16; k++) {
            float4 a0 = *(const float4*)&As[k][ty * 4];
            float4 a1 = *(const float4*)&As[k][64 + ty * 4];
            float4 b0 = *(const float4*)&Bs[k][tx * 4];
            float4 b1 = *(const float4*)&Bs[k][64 + tx * 4];
            float a[8]  = {a0.x, a0.y, a0.z, a0.w, a1.x, a1.y, a1.z, a1.w};
            float bv[8] = {b0.x, b0.y, b0.z, b0.w, b1.x, b1.y, b1.z, b1.w};
            #pragma unroll
            for (int i = 0; i < 8; i++)
                #pragma unroll
                for (int j = 0; j < 8; j++)
                    acc[i][j] += a[i] * bv[j];
        }
        __syncthreads();
    }

    #pragma unroll
    for (int i = 0; i < 8; i++) {
        int row = m0 + (i < 4 ? ty * 4 + i : 64 + ty * 4 + i - 4);
        if (row >= M) continue;
        float bval = bias ? bias[row] : 0.f;
        #pragma unroll
        for (int j = 0; j < 8; j++) {
            int col = n0 + (j < 4 ? tx * 4 + j : 64 + tx * 4 + j - 4);
            if (col >= N) continue;
            float v = acc[i][j] + bval;
            if (ACT == 1) v = gelu_f(v);
            if (ACT == 2) v += res[(size_t)row * N + col];
            C[(size_t)row * N + col] = v;
        }
    }
}

// ---------------------------------------------------------------------------
// Depthwise 3x3 conv, stride 2, pad 1, 128 channels, 4 maps.
// ---------------------------------------------------------------------------
__global__ void dwconv_kernel(const float* __restrict__ in, const float* __restrict__ w,
                              float* __restrict__ out, int Hin, int Hout, int total)
{
    int idx = blockIdx.x * blockDim.x + threadIdx.x;
    if (idx >= total) return;
    int ox = idx % Hout;
    int r  = idx / Hout;
    int oy = r % Hout;  r /= Hout;
    int c  = r & 127;
    int nc = r;         // n*128 + c
    const float* ip = in + (size_t)nc * Hin * Hin;
    const float* wp = w + c * 9;
    float acc = 0.f;
    #pragma unroll
    for (int ky = 0; ky < 3; ky++) {
        int iy = oy * 2 - 1 + ky;
        if ((unsigned)iy >= (unsigned)Hin) continue;
        #pragma unroll
        for (int kx = 0; kx < 3; kx++) {
            int ix = ox * 2 - 1 + kx;
            if ((unsigned)ix >= (unsigned)Hin) continue;
            acc += ip[iy * Hin + ix] * wp[ky * 3 + kx];
        }
    }
    out[idx] = acc;
}

// ---------------------------------------------------------------------------
// BatchNorm (inference) + exact GELU, in-place on (4,128,8,8).
// ---------------------------------------------------------------------------
__global__ void bngelu_kernel(float* __restrict__ o, const float* __restrict__ g,
                              const float* __restrict__ b, const float* __restrict__ m,
                              const float* __restrict__ v)
{
    int idx = blockIdx.x * blockDim.x + threadIdx.x;
    if (idx >= 32768) return;
    int c = (idx >> 6) & 127;
    float val = (o[idx] - m[c]) * rsqrtf(v[c] + 1e-5f) * g[c] + b[c];
    o[idx] = gelu_f(val);
}

// ---------------------------------------------------------------------------
// Sample positions (pixel space): pos[(n*64+w)*1024+r] = (row_px, col_px)
// off layout (n, 2048, 64): d=0 -> channel r, d=1 -> channel 1024+r.
// ---------------------------------------------------------------------------
__global__ void pos_kernel(const float* __restrict__ off, float2* __restrict__ pos)
{
    int idx = blockIdx.x * blockDim.x + threadIdx.x;
    if (idx >= 262144) return;
    int r = idx & 1023;
    int w = (idx >> 10) & 63;
    int n = idx >> 16;
    float v0 = off[(size_t)n * 131072 + (size_t)r * 64 + w];
    float v1 = off[(size_t)n * 131072 + (size_t)(1024 + r) * 64 + w];
    int ry = r >> 5, rx = r & 31;
    // tanh(off) * (1/64) * 2 + ref;   ref = idx*2/63*2 - 1
    float g0 = tanhf(v0) * 0.03125f + (4.0f * (float)ry / 63.0f - 1.0f);
    float g1 = tanhf(v1) * 0.03125f + (4.0f * (float)rx / 63.0f - 1.0f);
    float2 p;
    p.x = (g0 + 1.0f) * 0.5f * 63.0f;   // row
    p.y = (g1 + 1.0f) * 0.5f * 63.0f;   // col
    pos[idx] = p;
}

// ---------------------------------------------------------------------------
// Fused bilinear sample of the PROJECTED maps into kk/vv.
// kk[b,o,w,r] = k_b[o] + sum_g bilinear(kxa[b,g,o], pos[b*2+g, w, r])
// One thread per (b,w,r); geometry (weights/offsets/predicates) hoisted,
// loop over all 256 output channels o. OOB taps contribute 0.
// ---------------------------------------------------------------------------
__global__ void sample_kv_kernel(const float* __restrict__ kxa, const float* __restrict__ vxa,
                                 const float2* __restrict__ pos,
                                 const float* __restrict__ k_b, const float* __restrict__ v_b,
                                 float* __restrict__ kk, float* __restrict__ vv)
{
    int idx = blockIdx.x * blockDim.x + threadIdx.x;   // < 131072
    if (idx >= 131072) return;
    int r = idx & 1023;
    int w = (idx >> 10) & 63;
    int b = idx >> 16;

    // hoisted per-group geometry
    float wgt[2][4];
    int   ofs[2][4];
    bool  ok [2][4];
    #pragma unroll
    for (int g = 0; g < 2; g++) {
        int n = b * 2 + g;
        float2 p = pos[((n * 64 + w) << 10) | r];
        float r0f = floorf(p.x), c0f = floorf(p.y);
        float wr = p.x - r0f,    wc = p.y - c0f;
        int ir = (int)r0f, ic = (int)c0f;
        wgt[g][0] = (1.f - wr) * (1.f - wc);
        wgt[g][1] = (1.f - wr) * wc;
        wgt[g][2] = wr * (1.f - wc);
        wgt[g][3] = wr * wc;
        ofs[g][0] = ir * 64 + ic;
        ofs[g][1] = ir * 64 + ic + 1;
        ofs[g][2] = (ir + 1) * 64 + ic;
        ofs[g][3] = (ir + 1) * 64 + ic + 1;
        bool ry0 = (unsigned)ir < 64u, ry1 = (unsigned)(ir + 1) < 64u;
        bool cx0 = (unsigned)ic < 64u, cx1 = (unsigned)(ic + 1) < 64u;
        ok[g][0] = ry0 && cx0;  ok[g][1] = ry0 && cx1;
        ok[g][2] = ry1 && cx0;  ok[g][3] = ry1 && cx1;
    }

    // image bases for o=0; advance by 4096 per o. group1 is +256*4096 ahead.
    const float* k0 = kxa + ((size_t)(b * 2) * 256 << 12);
    const float* v0 = vxa + ((size_t)(b * 2) * 256 << 12);
    size_t outp = ((size_t)(b * 256) * 64 + w) * 1024 + r;

    for (int o = 0; o < 256; o++) {
        const float* ki0 = k0 + ((size_t)o << 12);
        const float* ki1 = ki0 + (256 << 12);
        const float* vi0 = v0 + ((size_t)o << 12);
        const float* vi1 = vi0 + (256 << 12);
        float ka = k_b[o], va = v_b[o];
        #pragma unroll
        for (int tp = 0; tp < 4; tp++) {
            if (ok[0][tp]) {
                ka += ki0[ofs[0][tp]] * wgt[0][tp];
                va += vi0[ofs[0][tp]] * wgt[0][tp];
            }
            if (ok[1][tp]) {
                ka += ki1[ofs[1][tp]] * wgt[1][tp];
                va += vi1[ofs[1][tp]] * wgt[1][tp];
            }
        }
        kk[outp] = ka;
        vv[outp] = va;
        outp += 65536;
    }
}

// ---------------------------------------------------------------------------
// Windowed deformable attention. One block per (window w, head-batch n).
// Flash-style streaming softmax over R=1024 in 8 chunks of 128.
// Thread layout: q = t>>2 (0..63), l4 = t&3.
//   QK: thread covers r = l4*32 .. l4*32+31 of the chunk.
//   AV: thread accumulates out[q][4k+l4], k=0..7.
// ---------------------------------------------------------------------------
#define ATTN_SMEM_FLOATS (64*33 + 32*132 + 32*132 + 64*132 + 70*71)
#define ATTN_SMEM_BYTES  (ATTN_SMEM_FLOATS * 4)

__global__ __launch_bounds__(256, 2)
void attn_kernel(const float* __restrict__ qt, const float* __restrict__ kk,
                 const float* __restrict__ vv, const float* __restrict__ pe,
                 float* __restrict__ outp)
{
    extern __shared__ float sm[];
    float* Qs = sm;               // [64][33]
    float* Ks = Qs + 64 * 33;     // [32][132]
    float* Vs = Ks + 32 * 132;    // [32][132]
    float* Ps = Vs + 32 * 132;    // [64][132]
    float* Pe = Ps + 64 * 132;    // [70][71]

    int w  = blockIdx.x;
    int n  = blockIdx.y;
    int b  = n >> 3, h = n & 7;
    int wh = w >> 3, wwi = w & 7;
    int y0 = wh * 8, x0 = wwi * 8;
    int t  = threadIdx.x;

    // posembed tile: rr = 2*ry - sy + 7 in [0,69]; global py = (56-y0)+rr
    {
        const float* peh = pe + h * 16129;          // 127*127
        int pymin = 56 - y0, pxmin = 56 - x0;
        for (int i = t; i < 4900; i += 256) {
            int rr = i / 70, cc = i - rr * 70;
            Pe[rr * 71 + cc] = peh[(pymin + rr) * 127 + pxmin + cc];
        }
    }
    // Q tile (scaled by DIM^-0.5 = 1/16)
    {
        int c = t >> 3, sy_ = t & 7;
        const float* src = qt + (((size_t)(b * 256 + h * 32 + c) * 64 + y0 + sy_) * 64 + x0);
        #pragma unroll
        for (int sx_ = 0; sx_ < 8; sx_++)
            Qs[(sy_ * 8 + sx_) * 33 + c] = src[sx_] * 0.0625f;
    }
    __syncthreads();

    int q = t >> 2, l4 = t & 3;
    float qreg[32];
    #pragma unroll
    for (int c = 0; c < 32; c++) qreg[c] = Qs[q * 33 + c];
    int sy = q >> 3, sx = q & 7;

    float m_run = -3.0e38f, l_run = 0.f;
    float oacc[8];
    #pragma unroll
    for (int k = 0; k < 8; k++) oacc[k] = 0.f;

    const float* kbase = kk + ((size_t)(b * 256 + h * 32) * 64 + w) * 1024;
    const float* vbase = vv + ((size_t)(b * 256 + h * 32) * 64 + w) * 1024;
    int rb = l4 * 32;

    for (int chn = 0; chn < 8; chn++) {
        int r0 = chn * 128;
        // load K,V chunk: [32 ch][128 r], coalesced along r
        {
            int c = t >> 3, rr0 = (t & 7) * 16;
            const float4* ksrc = (const float4*)(kbase + (size_t)c * 65536 + r0 + rr0);
            const float4* vsrc = (const float4*)(vbase + (size_t)c * 65536 + r0 + rr0);
            float4* kdst = (float4*)(Ks + c * 132 + rr0);
            float4* vdst = (float4*)(Vs + c * 132 + rr0);
            #pragma unroll
            for (int i = 0; i < 4; i++) { kdst[i] = ksrc[i]; vdst[i] = vsrc[i]; }
        }
        __syncthreads();

        // S = Q @ K for this thread's 32 r's, + bias
        float acc[32];
        #pragma unroll
        for (int j = 0; j < 32; j++) acc[j] = 0.f;
        #pragma unroll 4
        for (int c = 0; c < 32; c++) {
            float qv = qreg[c];
            const float4* krow = (const float4*)(Ks + c * 132 + rb);
            #pragma unroll
            for (int jj = 0; jj < 8; jj++) {
                float4 kv = krow[jj];
                acc[jj * 4 + 0] += qv * kv.x;
                acc[jj * 4 + 1] += qv * kv.y;
                acc[jj * 4 + 2] += qv * kv.z;
                acc[jj * 4 + 3] += qv * kv.w;
            }
        }
        #pragma unroll
        for (int j = 0; j < 32; j++) {
            int rg = r0 + rb + j;
            int ry = rg >> 5, rx = rg & 31;
            acc[j] += Pe[(2 * ry - sy + 7) * 71 + (2 * rx - sx + 7)];
        }

        // streaming softmax (per-q stats replicated across the 4 l4 lanes)
        float mc = acc[0];
        #pragma unroll
        for (int j = 1; j < 32; j++) mc = fmaxf(mc, acc[j]);
        mc = fmaxf(mc, __shfl_xor_sync(0xffffffffu, mc, 1));
        mc = fmaxf(mc, __shfl_xor_sync(0xffffffffu, mc, 2));
        float m_new = fmaxf(m_run, mc);
        float scl = __expf(m_run - m_new);
        float lc = 0.f;
        #pragma unroll
        for (int j = 0; j < 32; j++) {
            float p = __expf(acc[j] - m_new);
            acc[j] = p; lc += p;
        }
        lc += __shfl_xor_sync(0xffffffffu, lc, 1);
        lc += __shfl_xor_sync(0xffffffffu, lc, 2);
        l_run = l_run * scl + lc;
        m_run = m_new;
        #pragma unroll
        for (int k = 0; k < 8; k++) oacc[k] *= scl;

        // publish P
        #pragma unroll
        for (int j = 0; j < 32; j += 4)
            *(float4*)(Ps + q * 132 + rb + j) = *(float4*)(acc + j);
        __syncthreads();

        // AV: oacc[k] += sum_r P[q][r] * V[4k+l4][r]
        #pragma unroll 8
        for (int rr = 0; rr < 128; rr += 4) {
            float4 p4 = *(const float4*)(Ps + q * 132 + rr);
            #pragma unroll
            for (int k = 0; k < 8; k++) {
                float4 v4 = *(const float4*)(Vs + (4 * k + l4) * 132 + rr);
                oacc[k] += p4.x * v4.x + p4.y * v4.y + p4.z * v4.z + p4.w * v4.w;
            }
        }
        __syncthreads();   // before next chunk overwrites Ks/Vs
    }

    float inv = 1.0f / l_run;
    #pragma unroll
    for (int k = 0; k < 8; k++) {
        int c = 4 * k + l4;
        outp[((size_t)(b * 256 + h * 32 + c) * 64 + y0 + sy) * 64 + x0 + sx] = oacc[k] * inv;
    }
}

// ---------------------------------------------------------------------------
extern "C" void kernel_launch(void* const* d_in, const int* in_sizes, int n_in,
                              void* d_out, int out_size)
{
    const float* x       = (const float*)d_in[0];
    const float* ln1_g   = (const float*)d_in[1];
    const float* ln1_b   = (const float*)d_in[2];
    const float* q_w     = (const float*)d_in[3];
    const float* q_b     = (const float*)d_in[4];
    const float* k_w     = (const float*)d_in[5];
    const float* k_b     = (const float*)d_in[6];
    const float* v_w     = (const float*)d_in[7];
    const float* v_b     = (const float*)d_in[8];
    const float* off1_w  = (const float*)d_in[9];
    const float* off2_w  = (const float*)d_in[10];
    const float* off3_w  = (const float*)d_in[11];
    const float* bn_g    = (const float*)d_in[12];
    const float* bn_b    = (const float*)d_in[13];
    const float* bn_m    = (const float*)d_in[14];
    const float* bn_v    = (const float*)d_in[15];
    const float* off4_w  = (const float*)d_in[16];
    const float* posembed= (const float*)d_in[17];
    const float* proj_w  = (const float*)d_in[18];
    const float* proj_b  = (const float*)d_in[19];
    const float* ln2_g   = (const float*)d_in[20];
    const float* ln2_b   = (const float*)d_in[21];
    const float* mlp_w1  = (const float*)d_in[22];
    const float* mlp_b1  = (const float*)d_in[23];
    const float* mlp_w2  = (const float*)d_in[24];
    const float* mlp_b2  = (const float*)d_in[25];
    float* out = (float*)d_out;

    float  *xa, *qb_, *t1, *t2, *t3, *off, *kxa, *vxa, *kkp, *vvp, *ao, *x1, *xm, *hdn;
    float2 *pos;
    cudaGetSymbolAddress((void**)&xa,   g_xa);
    cudaGetSymbolAddress((void**)&qb_,  g_q);
    cudaGetSymbolAddress((void**)&t1,   g_t1);
    cudaGetSymbolAddress((void**)&t2,   g_t2);
    cudaGetSymbolAddress((void**)&t3,   g_t3);
    cudaGetSymbolAddress((void**)&off,  g_off);
    cudaGetSymbolAddress((void**)&pos,  g_pos);
    cudaGetSymbolAddress((void**)&kxa,  g_kxa);
    cudaGetSymbolAddress((void**)&vxa,  g_vxa);
    cudaGetSymbolAddress((void**)&kkp,  g_kk);
    cudaGetSymbolAddress((void**)&vvp,  g_vv);
    cudaGetSymbolAddress((void**)&ao,   g_ao);
    cudaGetSymbolAddress((void**)&x1,   g_x1);
    cudaGetSymbolAddress((void**)&xm,   g_xm);
    cudaGetSymbolAddress((void**)&hdn,  g_hdn);

    cudaFuncSetAttribute(attn_kernel, cudaFuncAttributeMaxDynamicSharedMemorySize,
                         ATTN_SMEM_BYTES);

    // 1) LN1
    ln_kernel<<<dim3(64, 2), 64>>>(x, ln1_g, ln1_b, xa);
    // 2) q = q_w @ xa + q_b
    sgemm_kernel<0><<<dim3(32, 2, 2), 256>>>(q_w, xa, qb_, q_b, nullptr,
                                             256, 4096, 256, 256, 4096,
                                             0, 1048576, 1048576, 0);
    // 3-5) depthwise stack 64->32->16->8 on q viewed as (4,128,64,64)
    dwconv_kernel<<<2048, 256>>>(qb_, off1_w, t1, 64, 32, 524288);
    dwconv_kernel<<<512, 256>>>(t1, off2_w, t2, 32, 16, 131072);
    dwconv_kernel<<<128, 256>>>(t2, off3_w, t3, 16, 8, 32768);
    // 6) BN + GELU
    bngelu_kernel<<<128, 256>>>(t3, bn_g, bn_b, bn_m, bn_v);
    // 7) off = off4_w @ t3  (per n: 2048x64x128)
    sgemm_kernel<0><<<dim3(1, 16, 4), 256>>>(off4_w, t3, off, nullptr, nullptr,
                                             2048, 64, 128, 128, 64,
                                             0, 8192, 131072, 0);
    // 8) sample positions
    pos_kernel<<<1024, 256>>>(off, pos);
    // 9) per-group projected maps: kxa[b,g] = k_w[:,g*128:] @ xa[b,g*128:,:]
    for (int g = 0; g < 2; g++) {
        sgemm_kernel<0><<<dim3(32, 2, 2), 256>>>(
            k_w + g * 128, xa + g * 524288, kxa + (size_t)g * 1048576,
            nullptr, nullptr, 256, 4096, 128, 256, 4096,
            0, 1048576, 2097152, 0);
        sgemm_kernel<0><<<dim3(32, 2, 2), 256>>>(
            v_w + g * 128, xa + g * 524288, vxa + (size_t)g * 1048576,
            nullptr, nullptr, 256, 4096, 128, 256, 4096,
            0, 1048576, 2097152, 0);
    }
    // 10) fused bilinear sample of projected maps -> kk, vv (+bias)
    sample_kv_kernel<<<512, 256>>>(kxa, vxa, pos, k_b, v_b, kkp, vvp);
    // 11) windowed attention
    attn_kernel<<<dim3(64, 16), 256, ATTN_SMEM_BYTES>>>(qb_, kkp, vvp, posembed, ao);
    // 12) proj + residual -> x1
    sgemm_kernel<2><<<dim3(32, 2, 2), 256>>>(proj_w, ao, x1, proj_b, x,
                                             256, 4096, 256, 256, 4096,
                                             0, 1048576, 1048576, 1048576);
    // 13) LN2
    ln_kernel<<<dim3(64, 2), 64>>>(x1, ln2_g, ln2_b, xm);
    // 14) MLP up + GELU
    sgemm_kernel<1><<<dim3(32, 8, 2), 256>>>(mlp_w1, xm, hdn, mlp_b1, nullptr,
                                             1024, 4096, 256, 256, 4096,
                                             0, 1048576, 4194304, 0);
    // 15) MLP down + residual -> out
    sgemm_kernel<2><<<dim3(32, 2, 2), 256>>>(mlp_w2, hdn, out, mlp_b2, x1,
                                             256, 4096, 1024, 1024, 4096,
                                             0, 4194304, 1048576, 1048576);
}

// round 17
// speedup vs baseline: 1.7311x; 1.7311x over previous
#include <cuda_runtime.h>
#include <math.h>

// ---------------------------------------------------------------------------
// CBiAFormerBlock: B=2, DIM=256, H=W=64, HEADS=8, HG=2, GC=128, HC=32,
// STRIDE=2, WS=8, RH=RW=32 (R=1024), WH=WW=8 (NW=64), WT=64, MLP_HID=1024.
//
// R7 restructure: channel-contiguous sampling.
//  - kxa/vxa transposed to pixel-major (map, px, 256ch)
//  - sample_kv: one WARP per sample point, lanes over channels -> all loads
//    and stores coalesced (was: ~30x L1 wavefront replay on scattered gathers)
//  - kk/vv layout now (point, channel); attention adapted, with conflict-free
//    QK (r = j*4+l4 interleave) and AV (c = l4*8+k) smem access.
// ---------------------------------------------------------------------------

// ------------------------- scratch (device globals) ------------------------
__device__ float  g_xa  [2097152];    // LN1(x)          (B,256,64,64)
__device__ float  g_q   [2097152];    // q conv          (B,256,64,64)
__device__ float  g_t1  [524288];     // dw1             (4,128,32,32)
__device__ float  g_t2  [131072];     // dw2             (4,128,16,16)
__device__ float  g_t3  [32768];      // dw3 + bn/gelu   (4,128,8,8)
__device__ float  g_off [524288];     // off4 gemm       (4,2048,64)
__device__ float2 g_pos [262144];     // sample coords   (4,64,1024)
__device__ float  g_kxa [4194304];    // k_w@xa per grp  (4,256,4096) ch-major
__device__ float  g_vxa [4194304];    // v_w@xa per grp  (4,256,4096) ch-major
__device__ float  g_ktx [4194304];    // transposed      (4,4096,256) px-major
__device__ float  g_vtx [4194304];    // transposed      (4,4096,256) px-major
__device__ float  g_kk  [33554432];   // sampled k       (point=B*64*1024, 256)
__device__ float  g_vv  [33554432];   // sampled v       (point, 256)
__device__ float  g_ao  [2097152];    // attn out        (B,256,64,64)
__device__ float  g_x1  [2097152];    // x + proj
__device__ float  g_xm  [2097152];    // LN2(x1)
__device__ float  g_hdn [8388608];    // mlp hidden      (B,1024,64,64)

__device__ __forceinline__ float gelu_f(float v) {
    return 0.5f * v * (1.0f + erff(v * 0.7071067811865476f));
}

// ---------------------------------------------------------------------------
// LayerNorm over channel dim (256) per pixel. grid(64, B), block 64 (x-pixel)
// ---------------------------------------------------------------------------
__global__ void ln_kernel(const float* __restrict__ x, const float* __restrict__ g,
                          const float* __restrict__ bb, float* __restrict__ out)
{
    int px = threadIdx.x;
    int y  = blockIdx.x;
    int b  = blockIdx.y;
    const float* base = x + (size_t)b * 1048576 + y * 64 + px;
    float s = 0.f, s2 = 0.f;
    #pragma unroll 4
    for (int c = 0; c < 256; c++) {
        float v = base[(size_t)c * 4096];
        s += v; s2 += v * v;
    }
    float mu   = s * (1.0f / 256.0f);
    float var  = s2 * (1.0f / 256.0f) - mu * mu;
    float rstd = rsqrtf(var + 1e-5f);
    float* ob = out + (size_t)b * 1048576 + y * 64 + px;
    #pragma unroll 4
    for (int c = 0; c < 256; c++) {
        float v = base[(size_t)c * 4096];
        ob[(size_t)c * 4096] = (v - mu) * rstd * g[c] + bb[c];
    }
}

// ---------------------------------------------------------------------------
// Generic SGEMM: C[M,N] = act(A[M,K] @ B[K,N] + bias[M]) (+res)
// ---------------------------------------------------------------------------
template<int ACT>
__global__ __launch_bounds__(256, 2)
void sgemm_kernel(const float* __restrict__ A, const float* __restrict__ B,
                  float* __restrict__ C, const float* __restrict__ bias,
                  const float* __restrict__ res,
                  int M, int N, int K, int lda, int ldb,
                  long long sA, long long sB, long long sC, long long sR)
{
    __shared__ float As[16][132];
    __shared__ float Bs[16][128];

    int bz = blockIdx.z;
    A += bz * sA; B += bz * sB; C += bz * sC;
    if (ACT == 2) res += bz * sR;

    int n0 = blockIdx.x * 128, m0 = blockIdx.y * 128;
    int t  = threadIdx.x;
    int tx = t & 15, ty = t >> 4;

    float acc[8][8];
    #pragma unroll
    for (int i = 0; i < 8; i++)
        #pragma unroll
        for (int j = 0; j < 8; j++) acc[i][j] = 0.f;

    int ar = t >> 1, ks = (t & 1) * 8;
    int br = t >> 4, bc = (t & 15) * 8;

    for (int k0 = 0; k0 < K; k0 += 16) {
        int arow = m0 + ar;
        const float* ap = A + (size_t)arow * lda + k0 + ks;
        #pragma unroll
        for (int i = 0; i < 8; i++)
            As[ks + i][ar] = (arow < M) ? ap[i] : 0.f;

        const float* bp = B + (size_t)(k0 + br) * ldb + n0 + bc;
        #pragma unroll
        for (int i = 0; i < 8; i++)
            Bs[br][bc + i] = (n0 + bc + i < N) ? bp[i] : 0.f;

        __syncthreads();
        #pragma unroll
        for (int k = 0; k < 16; k++) {
            float4 a0 = *(const float4*)&As[k][ty * 4];
            float4 a1 = *(const float4*)&As[k][64 + ty * 4];
            float4 b0 = *(const float4*)&Bs[k][tx * 4];
            float4 b1 = *(const float4*)&Bs[k][64 + tx * 4];
            float a[8]  = {a0.x, a0.y, a0.z, a0.w, a1.x, a1.y, a1.z, a1.w};
            float bv[8] = {b0.x, b0.y, b0.z, b0.w, b1.x, b1.y, b1.z, b1.w};
            #pragma unroll
            for (int i = 0; i < 8; i++)
                #pragma unroll
                for (int j = 0; j < 8; j++)
                    acc[i][j] += a[i] * bv[j];
        }
        __syncthreads();
    }

    #pragma unroll
    for (int i = 0; i < 8; i++) {
        int row = m0 + (i < 4 ? ty * 4 + i : 64 + ty * 4 + i - 4);
        if (row >= M) continue;
        float bval = bias ? bias[row] : 0.f;
        #pragma unroll
        for (int j = 0; j < 8; j++) {
            int col = n0 + (j < 4 ? tx * 4 + j : 64 + tx * 4 + j - 4);
            if (col >= N) continue;
            float v = acc[i][j] + bval;
            if (ACT == 1) v = gelu_f(v);
            if (ACT == 2) v += res[(size_t)row * N + col];
            C[(size_t)row * N + col] = v;
        }
    }
}

// ---------------------------------------------------------------------------
// Depthwise 3x3 conv, stride 2, pad 1, 128 channels, 4 maps.
// ---------------------------------------------------------------------------
__global__ void dwconv_kernel(const float* __restrict__ in, const float* __restrict__ w,
                              float* __restrict__ out, int Hin, int Hout, int total)
{
    int idx = blockIdx.x * blockDim.x + threadIdx.x;
    if (idx >= total) return;
    int ox = idx % Hout;
    int r  = idx / Hout;
    int oy = r % Hout;  r /= Hout;
    int c  = r & 127;
    int nc = r;
    const float* ip = in + (size_t)nc * Hin * Hin;
    const float* wp = w + c * 9;
    float acc = 0.f;
    #pragma unroll
    for (int ky = 0; ky < 3; ky++) {
        int iy = oy * 2 - 1 + ky;
        if ((unsigned)iy >= (unsigned)Hin) continue;
        #pragma unroll
        for (int kx = 0; kx < 3; kx++) {
            int ix = ox * 2 - 1 + kx;
            if ((unsigned)ix >= (unsigned)Hin) continue;
            acc += ip[iy * Hin + ix] * wp[ky * 3 + kx];
        }
    }
    out[idx] = acc;
}

// ---------------------------------------------------------------------------
// BatchNorm (inference) + exact GELU, in-place on (4,128,8,8).
// ---------------------------------------------------------------------------
__global__ void bngelu_kernel(float* __restrict__ o, const float* __restrict__ g,
                              const float* __restrict__ b, const float* __restrict__ m,
                              const float* __restrict__ v)
{
    int idx = blockIdx.x * blockDim.x + threadIdx.x;
    if (idx >= 32768) return;
    int c = (idx >> 6) & 127;
    float val = (o[idx] - m[c]) * rsqrtf(v[c] + 1e-5f) * g[c] + b[c];
    o[idx] = gelu_f(val);
}

// ---------------------------------------------------------------------------
// Sample positions (pixel space).
// ---------------------------------------------------------------------------
__global__ void pos_kernel(const float* __restrict__ off, float2* __restrict__ pos)
{
    int idx = blockIdx.x * blockDim.x + threadIdx.x;
    if (idx >= 262144) return;
    int r = idx & 1023;
    int w = (idx >> 10) & 63;
    int n = idx >> 16;
    float v0 = off[(size_t)n * 131072 + (size_t)r * 64 + w];
    float v1 = off[(size_t)n * 131072 + (size_t)(1024 + r) * 64 + w];
    int ry = r >> 5, rx = r & 31;
    float g0 = tanhf(v0) * 0.03125f + (4.0f * (float)ry / 63.0f - 1.0f);
    float g1 = tanhf(v1) * 0.03125f + (4.0f * (float)rx / 63.0f - 1.0f);
    float2 p;
    p.x = (g0 + 1.0f) * 0.5f * 63.0f;   // row
    p.y = (g1 + 1.0f) * 0.5f * 63.0f;   // col
    pos[idx] = p;
}

// ---------------------------------------------------------------------------
// Tiled transpose: (map, 256ch, 4096px) -> (map, 4096px, 256ch).
// grid (128, 8, 8): z<4 -> k maps, z>=4 -> v maps. block (32, 8).
// ---------------------------------------------------------------------------
__global__ void transpose_kernel(const float* __restrict__ kin, const float* __restrict__ vin,
                                 float* __restrict__ kout, float* __restrict__ vout)
{
    __shared__ float tile[32][33];
    int z = blockIdx.z;
    const float* in = (z < 4) ? kin + (size_t)z * 1048576 : vin + (size_t)(z - 4) * 1048576;
    float* out      = (z < 4) ? kout + (size_t)z * 1048576 : vout + (size_t)(z - 4) * 1048576;
    int px0 = blockIdx.x * 32, ch0 = blockIdx.y * 32;
    int tx = threadIdx.x, ty = threadIdx.y;
    #pragma unroll
    for (int i = 0; i < 32; i += 8)
        tile[ty + i][tx] = in[(size_t)(ch0 + ty + i) * 4096 + px0 + tx];
    __syncthreads();
    #pragma unroll
    for (int i = 0; i < 32; i += 8)
        out[(size_t)(px0 + ty + i) * 256 + ch0 + tx] = tile[tx][ty + i];
}

// ---------------------------------------------------------------------------
// Warp-per-point bilinear sample from pixel-major projected maps.
// wid = b*65536 + w*1024 + r; lane handles channels o = lane*8 .. lane*8+7.
// kk/vv layout: [point][256ch]. grid 16384 x 256.
// ---------------------------------------------------------------------------
__global__ __launch_bounds__(256)
void sample_kv_kernel(const float* __restrict__ ktx, const float* __restrict__ vtx,
                      const float2* __restrict__ pos,
                      const float* __restrict__ k_b, const float* __restrict__ v_b,
                      float* __restrict__ kk, float* __restrict__ vv)
{
    int wid  = (blockIdx.x << 3) + (threadIdx.x >> 5);   // 0..131071
    int lane = threadIdx.x & 31;
    int r = wid & 1023, w = (wid >> 10) & 63, b = wid >> 16;
    int o = lane * 8;

    float4 ka0 = ((const float4*)k_b)[lane * 2];
    float4 ka1 = ((const float4*)k_b)[lane * 2 + 1];
    float4 va0 = ((const float4*)v_b)[lane * 2];
    float4 va1 = ((const float4*)v_b)[lane * 2 + 1];

    #pragma unroll
    for (int g = 0; g < 2; g++) {
        int n = b * 2 + g;
        float2 p = pos[((n * 64 + w) << 10) | r];
        float r0f = floorf(p.x), c0f = floorf(p.y);
        float wr = p.x - r0f,    wc = p.y - c0f;
        int ir = (int)r0f, ic = (int)c0f;
        float wt[4] = {(1.f - wr) * (1.f - wc), (1.f - wr) * wc,
                       wr * (1.f - wc),          wr * wc};
        int px[4] = {ir * 64 + ic, ir * 64 + ic + 1,
                     (ir + 1) * 64 + ic, (ir + 1) * 64 + ic + 1};
        bool ry0 = (unsigned)ir < 64u, ry1 = (unsigned)(ir + 1) < 64u;
        bool cx0 = (unsigned)ic < 64u, cx1 = (unsigned)(ic + 1) < 64u;
        bool ok[4] = {ry0 && cx0, ry0 && cx1, ry1 && cx0, ry1 && cx1};

        const float* kb = ktx + (size_t)n * 1048576;
        const float* vb = vtx + (size_t)n * 1048576;
        #pragma unroll
        for (int tp = 0; tp < 4; tp++) {
            if (ok[tp]) {                               // warp-uniform branch
                size_t a = (size_t)px[tp] * 256 + o;
                float4 k0 = *(const float4*)(kb + a);
                float4 k1 = *(const float4*)(kb + a + 4);
                float4 v0 = *(const float4*)(vb + a);
                float4 v1 = *(const float4*)(vb + a + 4);
                float wg = wt[tp];
                ka0.x += wg * k0.x; ka0.y += wg * k0.y; ka0.z += wg * k0.z; ka0.w += wg * k0.w;
                ka1.x += wg * k1.x; ka1.y += wg * k1.y; ka1.z += wg * k1.z; ka1.w += wg * k1.w;
                va0.x += wg * v0.x; va0.y += wg * v0.y; va0.z += wg * v0.z; va0.w += wg * v0.w;
                va1.x += wg * v1.x; va1.y += wg * v1.y; va1.z += wg * v1.z; va1.w += wg * v1.w;
            }
        }
    }

    size_t outb = (size_t)wid * 256 + o;
    *(float4*)(kk + outb)     = ka0;
    *(float4*)(kk + outb + 4) = ka1;
    *(float4*)(vv + outb)     = va0;
    *(float4*)(vv + outb + 4) = va1;
}

// ---------------------------------------------------------------------------
// Windowed deformable attention on (point, channel)-layout kk/vv.
// Block per (window w, head-batch n). Flash softmax over R=1024, 8x128 chunks.
// Thread (q = t>>2, l4 = t&3):
//   QK: r_local = j*4 + l4, j = 0..31 (conflict-free smem reads)
//   AV: channels c = l4*8 + k, k = 0..7 (conflict-free float4 V reads)
// ---------------------------------------------------------------------------
#define ATTN_SMEM_FLOATS (64*33 + 128*36 + 128*36 + 64*132 + 70*71)
#define ATTN_SMEM_BYTES  (ATTN_SMEM_FLOATS * 4)

__global__ __launch_bounds__(256, 2)
void attn_kernel(const float* __restrict__ qt, const float* __restrict__ kk,
                 const float* __restrict__ vv, const float* __restrict__ pe,
                 float* __restrict__ outp)
{
    extern __shared__ float sm[];
    float* Qs = sm;                // [64][33]
    float* Ks = Qs + 64 * 33;      // [128 r][36 ch]
    float* Vs = Ks + 128 * 36;     // [128 r][36 ch]
    float* Ps = Vs + 128 * 36;     // [64 q][132 r]
    float* Pe = Ps + 64 * 132;     // [70][71]

    int w  = blockIdx.x;
    int n  = blockIdx.y;
    int b  = n >> 3, h = n & 7;
    int y0 = (w >> 3) * 8, x0 = (w & 7) * 8;
    int t  = threadIdx.x;

    // posembed tile (always in-bounds: global idx <= 125 < 127)
    {
        const float* peh = pe + h * 16129;
        int pymin = 56 - y0, pxmin = 56 - x0;
        for (int i = t; i < 4900; i += 256) {
            int rr = i / 70, cc = i - rr * 70;
            Pe[rr * 71 + cc] = peh[(pymin + rr) * 127 + pxmin + cc];
        }
    }
    // Q tile (scaled by 1/16)
    {
        int c = t >> 3, sy_ = t & 7;
        const float* src = qt + (((size_t)(b * 256 + h * 32 + c) * 64 + y0 + sy_) * 64 + x0);
        #pragma unroll
        for (int sx_ = 0; sx_ < 8; sx_++)
            Qs[(sy_ * 8 + sx_) * 33 + c] = src[sx_] * 0.0625f;
    }
    __syncthreads();

    int q = t >> 2, l4 = t & 3;
    float qreg[32];
    #pragma unroll
    for (int c = 0; c < 32; c++) qreg[c] = Qs[q * 33 + c];
    int sy = q >> 3, sx = q & 7;

    float m_run = -3.0e38f, l_run = 0.f;
    float oacc[8];
    #pragma unroll
    for (int k = 0; k < 8; k++) oacc[k] = 0.f;

    size_t pt_base = (size_t)(b * 64 + w) * 1024;
    const float* kbase = kk + pt_base * 256 + h * 32;
    const float* vbase = vv + pt_base * 256 + h * 32;

    int lrow = t >> 3;          // 0..31 loader row
    int lf4  = (t & 7) * 4;     // 0..28 float offset within 32-ch slice

    for (int chn = 0; chn < 8; chn++) {
        int r0 = chn * 128;
        // load K,V chunk: 128 rows x 32 ch; 1 gmem line per row (optimal)
        #pragma unroll
        for (int p = 0; p < 4; p++) {
            int row = p * 32 + lrow;
            float4 k4 = *(const float4*)(kbase + (size_t)(r0 + row) * 256 + lf4);
            float4 v4 = *(const float4*)(vbase + (size_t)(r0 + row) * 256 + lf4);
            *(float4*)(Ks + row * 36 + lf4) = k4;
            *(float4*)(Vs + row * 36 + lf4) = v4;
        }
        __syncthreads();

        // QK + bias for r_local = j*4 + l4
        float acc[32];
        #pragma unroll 4
        for (int j = 0; j < 32; j++) {
            const float* krow = Ks + (j * 4 + l4) * 36;
            float s = 0.f;
            #pragma unroll
            for (int c4 = 0; c4 < 8; c4++) {
                float4 kv = *(const float4*)(krow + c4 * 4);
                s += qreg[c4 * 4 + 0] * kv.x + qreg[c4 * 4 + 1] * kv.y
                   + qreg[c4 * 4 + 2] * kv.z + qreg[c4 * 4 + 3] * kv.w;
            }
            int rg = r0 + j * 4 + l4;
            int ry = rg >> 5, rx = rg & 31;
            acc[j] = s + Pe[(2 * ry - sy + 7) * 71 + (2 * rx - sx + 7)];
        }

        // streaming softmax (stats replicated across the 4 l4 lanes)
        float mc = acc[0];
        #pragma unroll
        for (int j = 1; j < 32; j++) mc = fmaxf(mc, acc[j]);
        mc = fmaxf(mc, __shfl_xor_sync(0xffffffffu, mc, 1));
        mc = fmaxf(mc, __shfl_xor_sync(0xffffffffu, mc, 2));
        float m_new = fmaxf(m_run, mc);
        float scl = __expf(m_run - m_new);
        float lc = 0.f;
        #pragma unroll
        for (int j = 0; j < 32; j++) {
            float p = __expf(acc[j] - m_new);
            acc[j] = p; lc += p;
        }
        lc += __shfl_xor_sync(0xffffffffu, lc, 1);
        lc += __shfl_xor_sync(0xffffffffu, lc, 2);
        l_run = l_run * scl + lc;
        m_run = m_new;
        #pragma unroll
        for (int k = 0; k < 8; k++) oacc[k] *= scl;

        // publish P (conflict-free: (4q + l4) distinct mod 32)
        #pragma unroll
        for (int j = 0; j < 32; j++)
            Ps[q * 132 + j * 4 + l4] = acc[j];
        __syncthreads();

        // AV: oacc[k] += sum_r P[q][r] * V[r][l4*8+k]
        #pragma unroll 4
        for (int rr4 = 0; rr4 < 32; rr4++) {
            float4 p4 = *(const float4*)(Ps + q * 132 + rr4 * 4);
            float pv[4] = {p4.x, p4.y, p4.z, p4.w};
            #pragma unroll
            for (int i = 0; i < 4; i++) {
                const float* vrow = Vs + (rr4 * 4 + i) * 36 + l4 * 8;
                float4 va = *(const float4*)(vrow);
                float4 vb = *(const float4*)(vrow + 4);
                oacc[0] += pv[i] * va.x; oacc[1] += pv[i] * va.y;
                oacc[2] += pv[i] * va.z; oacc[3] += pv[i] * va.w;
                oacc[4] += pv[i] * vb.x; oacc[5] += pv[i] * vb.y;
                oacc[6] += pv[i] * vb.z; oacc[7] += pv[i] * vb.w;
            }
        }
        __syncthreads();   // before next chunk overwrites Ks/Vs
    }

    float inv = 1.0f / l_run;
    #pragma unroll
    for (int k = 0; k < 8; k++) {
        int c = l4 * 8 + k;
        outp[((size_t)(b * 256 + h * 32 + c) * 64 + y0 + sy) * 64 + x0 + sx] = oacc[k] * inv;
    }
}

// ---------------------------------------------------------------------------
extern "C" void kernel_launch(void* const* d_in, const int* in_sizes, int n_in,
                              void* d_out, int out_size)
{
    const float* x       = (const float*)d_in[0];
    const float* ln1_g   = (const float*)d_in[1];
    const float* ln1_b   = (const float*)d_in[2];
    const float* q_w     = (const float*)d_in[3];
    const float* q_b     = (const float*)d_in[4];
    const float* k_w     = (const float*)d_in[5];
    const float* k_b     = (const float*)d_in[6];
    const float* v_w     = (const float*)d_in[7];
    const float* v_b     = (const float*)d_in[8];
    const float* off1_w  = (const float*)d_in[9];
    const float* off2_w  = (const float*)d_in[10];
    const float* off3_w  = (const float*)d_in[11];
    const float* bn_g    = (const float*)d_in[12];
    const float* bn_b    = (const float*)d_in[13];
    const float* bn_m    = (const float*)d_in[14];
    const float* bn_v    = (const float*)d_in[15];
    const float* off4_w  = (const float*)d_in[16];
    const float* posembed= (const float*)d_in[17];
    const float* proj_w  = (const float*)d_in[18];
    const float* proj_b  = (const float*)d_in[19];
    const float* ln2_g   = (const float*)d_in[20];
    const float* ln2_b   = (const float*)d_in[21];
    const float* mlp_w1  = (const float*)d_in[22];
    const float* mlp_b1  = (const float*)d_in[23];
    const float* mlp_w2  = (const float*)d_in[24];
    const float* mlp_b2  = (const float*)d_in[25];
    float* out = (float*)d_out;

    float  *xa, *qb_, *t1, *t2, *t3, *off, *kxa, *vxa, *ktx, *vtx,
           *kkp, *vvp, *ao, *x1, *xm, *hdn;
    float2 *pos;
    cudaGetSymbolAddress((void**)&xa,   g_xa);
    cudaGetSymbolAddress((void**)&qb_,  g_q);
    cudaGetSymbolAddress((void**)&t1,   g_t1);
    cudaGetSymbolAddress((void**)&t2,   g_t2);
    cudaGetSymbolAddress((void**)&t3,   g_t3);
    cudaGetSymbolAddress((void**)&off,  g_off);
    cudaGetSymbolAddress((void**)&pos,  g_pos);
    cudaGetSymbolAddress((void**)&kxa,  g_kxa);
    cudaGetSymbolAddress((void**)&vxa,  g_vxa);
    cudaGetSymbolAddress((void**)&ktx,  g_ktx);
    cudaGetSymbolAddress((void**)&vtx,  g_vtx);
    cudaGetSymbolAddress((void**)&kkp,  g_kk);
    cudaGetSymbolAddress((void**)&vvp,  g_vv);
    cudaGetSymbolAddress((void**)&ao,   g_ao);
    cudaGetSymbolAddress((void**)&x1,   g_x1);
    cudaGetSymbolAddress((void**)&xm,   g_xm);
    cudaGetSymbolAddress((void**)&hdn,  g_hdn);

    cudaFuncSetAttribute(attn_kernel, cudaFuncAttributeMaxDynamicSharedMemorySize,
                         ATTN_SMEM_BYTES);

    // 1) LN1
    ln_kernel<<<dim3(64, 2), 64>>>(x, ln1_g, ln1_b, xa);
    // 2) q = q_w @ xa + q_b
    sgemm_kernel<0><<<dim3(32, 2, 2), 256>>>(q_w, xa, qb_, q_b, nullptr,
                                             256, 4096, 256, 256, 4096,
                                             0, 1048576, 1048576, 0);
    // 3-5) depthwise stack 64->32->16->8 on q viewed as (4,128,64,64)
    dwconv_kernel<<<2048, 256>>>(qb_, off1_w, t1, 64, 32, 524288);
    dwconv_kernel<<<512, 256>>>(t1, off2_w, t2, 32, 16, 131072);
    dwconv_kernel<<<128, 256>>>(t2, off3_w, t3, 16, 8, 32768);
    // 6) BN + GELU
    bngelu_kernel<<<128, 256>>>(t3, bn_g, bn_b, bn_m, bn_v);
    // 7) off = off4_w @ t3
    sgemm_kernel<0><<<dim3(1, 16, 4), 256>>>(off4_w, t3, off, nullptr, nullptr,
                                             2048, 64, 128, 128, 64,
                                             0, 8192, 131072, 0);
    // 8) sample positions
    pos_kernel<<<1024, 256>>>(off, pos);
    // 9) per-group projected maps (channel-major)
    for (int g = 0; g < 2; g++) {
        sgemm_kernel<0><<<dim3(32, 2, 2), 256>>>(
            k_w + g * 128, xa + g * 524288, kxa + (size_t)g * 1048576,
            nullptr, nullptr, 256, 4096, 128, 256, 4096,
            0, 1048576, 2097152, 0);
        sgemm_kernel<0><<<dim3(32, 2, 2), 256>>>(
            v_w + g * 128, xa + g * 524288, vxa + (size_t)g * 1048576,
            nullptr, nullptr, 256, 4096, 128, 256, 4096,
            0, 1048576, 2097152, 0);
    }
    // 9b) transpose to pixel-major
    transpose_kernel<<<dim3(128, 8, 8), dim3(32, 8)>>>(kxa, vxa, ktx, vtx);
    // 10) warp-per-point bilinear sample -> kk/vv (point, channel)
    sample_kv_kernel<<<16384, 256>>>(ktx, vtx, pos, k_b, v_b, kkp, vvp);
    // 11) windowed attention
    attn_kernel<<<dim3(64, 16), 256, ATTN_SMEM_BYTES>>>(qb_, kkp, vvp, posembed, ao);
    // 12) proj + residual -> x1
    sgemm_kernel<2><<<dim3(32, 2, 2), 256>>>(proj_w, ao, x1, proj_b, x,
                                             256, 4096, 256, 256, 4096,
                                             0, 1048576, 1048576, 1048576);
    // 13) LN2
    ln_kernel<<<dim3(64, 2), 64>>>(x1, ln2_g, ln2_b, xm);
    // 14) MLP up + GELU
    sgemm_kernel<1><<<dim3(32, 8, 2), 256>>>(mlp_w1, xm, hdn, mlp_b1, nullptr,
                                             1024, 4096, 256, 256, 4096,
                                             0, 1048576, 4194304, 0);
    // 15) MLP down + residual -> out
    sgemm_kernel<2><<<dim3(32, 2, 2), 256>>>(mlp_w2, hdn, out, mlp_b2, x1,
                                             256, 4096, 1024, 1024, 4096,
                                             0, 4194304, 1048576, 1048576);
}